// round 1
// baseline (speedup 1.0000x reference)
#include <cuda_runtime.h>
#include <math.h>

// VectorQuantizer: N=65536 points (B=64,H=32,W=32 flattened BHWC), C=64, K=1024.
// Output layout (float32): [quantized 4194304][vq_loss 1][indices 65536][perplexity 1]
//
// Numerical contract (replicating jax/XLA-CPU fp32 semantics):
//  - dot(x,e_k): sequential-c fp32 FMA, single accumulator (Eigen gebp order)
//  - a = sum(x*x): sequential-c fp32: rn(mul) then rn(add)  [hypothesis #1]
//  - d = rn( rn(a - rn(2*dot)) + esq_k )
//  - argmin with first-index tie-break
//  - quantized_st = rn(x + rn(q - x))

#define NPTS   65536
#define KC     1024
#define CD     64
#define HW     1024
#define MT     128
#define XSTRIDE 132
#define ESTRIDE 68
#define SMEM_FLOATS (CD*XSTRIDE + 128*ESTRIDE + 128)
#define SMEM_BYTES  (SMEM_FLOATS * 4)

#define OFF_LOSS  4194304
#define OFF_IDX   4194305
#define OFF_PERP  4259841

typedef unsigned long long u64;

__device__ float        g_esq[KC];
__device__ int          g_idx[NPTS];
__device__ unsigned int g_hist[KC];
__device__ double       g_loss;

__device__ __forceinline__ u64 pack2(float lo, float hi) {
    u64 r; asm("mov.b64 %0, {%1, %2};" : "=l"(r) : "f"(lo), "f"(hi)); return r;
}
__device__ __forceinline__ u64 pack_dup(float x) {
    u64 r; asm("mov.b64 %0, {%1, %1};" : "=l"(r) : "f"(x)); return r;
}
__device__ __forceinline__ void unpack2(u64 v, float &lo, float &hi) {
    asm("mov.b64 {%0, %1}, %2;" : "=f"(lo), "=f"(hi) : "l"(v));
}
// packed fp32x2 FMA: each lane is an IEEE-rn fp32 fused multiply-add (bit-identical to FFMA)
__device__ __forceinline__ void ffma2(u64 &acc, u64 a, u64 b) {
    asm("fma.rn.f32x2 %0, %1, %2, %0;" : "+l"(acc) : "l"(a), "l"(b));
}

// ---------------- init ----------------
__global__ void vq_init() {
    int t = blockIdx.x * blockDim.x + threadIdx.x;
    if (t < KC) g_hist[t] = 0u;
    if (t == 0) g_loss = 0.0;
}

// ---------------- esq[k] = sum_c e^2 (sequential fp32, mul then add) ----------------
__global__ void vq_esq(const float* __restrict__ emb) {
    int k = blockIdx.x * blockDim.x + threadIdx.x;
    if (k < KC) {
        float s = 0.0f;
        const float* er = emb + (size_t)k * CD;
        #pragma unroll
        for (int c = 0; c < CD; ++c) {
            float e = er[c];
            s = __fadd_rn(s, __fmul_rn(e, e));
        }
        g_esq[k] = s;
    }
}

// ---------------- main: distances + argmin ----------------
__global__ void __launch_bounds__(256) vq_main(const float* __restrict__ inputs,
                                               const float* __restrict__ emb,
                                               float* __restrict__ outIdxF) {
    extern __shared__ float sm[];
    float* xs  = sm;                     // [CD][XSTRIDE]   xs[c*XSTRIDE + p]
    float* es  = sm + CD * XSTRIDE;      // [128][ESTRIDE]  es[kk*ESTRIDE + c]
    float* as_ = es + 128 * ESTRIDE;     // [128]

    const int t  = threadIdx.x;
    const int tr = t >> 4;    // 0..15 point group (8 pts each)
    const int tc = t & 15;    // 0..15 code lane
    const int n0 = blockIdx.x * MT;
    const int b  = n0 >> 10;
    const int p0 = n0 & 1023;
    const float* xbase = inputs + (size_t)b * (CD * HW) + p0;

    // load x tile (transposed into [c][p])
    #pragma unroll
    for (int j = 0; j < 8; ++j) {
        int q  = t + j * 256;
        int c  = q >> 5;
        int i4 = (q & 31) << 2;
        float4 v = *reinterpret_cast<const float4*>(xbase + (size_t)c * HW + i4);
        *reinterpret_cast<float4*>(&xs[c * XSTRIDE + i4]) = v;
    }
    __syncthreads();

    // a = ||x||^2 : strictly sequential fp32 (hypothesis: XLA CPU scalar reduce order)
    if (t < MT) {
        float s = 0.0f;
        #pragma unroll
        for (int c = 0; c < CD; ++c) {
            float xv = xs[c * XSTRIDE + t];
            s = __fadd_rn(s, __fmul_rn(xv, xv));
        }
        as_[t] = s;
    }

    float bestv[8];
    int   besti[8];
    #pragma unroll
    for (int i = 0; i < 8; ++i) { bestv[i] = __int_as_float(0x7f800000); besti[i] = 0x7fffffff; }

    #pragma unroll 1
    for (int kc = 0; kc < 8; ++kc) {
        __syncthreads();   // es reuse (and as_ visibility on first iter)
        // load e chunk: es[kk][c] = emb[(kc*128+kk)*64 + c]
        #pragma unroll
        for (int j = 0; j < 8; ++j) {
            int q  = t + j * 256;
            int kk = q >> 4;
            int cg = (q & 15) << 2;
            float4 v = *reinterpret_cast<const float4*>(emb + (size_t)(kc * 128 + kk) * CD + cg);
            *reinterpret_cast<float4*>(&es[kk * ESTRIDE + cg]) = v;
        }
        __syncthreads();

        u64 acc[8][4];
        #pragma unroll
        for (int j = 0; j < 8; ++j)
            #pragma unroll
            for (int i = 0; i < 4; ++i) acc[j][i] = 0ULL;

        #pragma unroll 4
        for (int c4 = 0; c4 < CD; c4 += 4) {
            float4 ef[8];
            #pragma unroll
            for (int j = 0; j < 8; ++j)
                ef[j] = *reinterpret_cast<const float4*>(&es[(j * 16 + tc) * ESTRIDE + c4]);
            #pragma unroll
            for (int cc = 0; cc < 4; ++cc) {
                const float* xr = &xs[(c4 + cc) * XSTRIDE + tr * 8];
                float4 u0 = *reinterpret_cast<const float4*>(xr);
                float4 u1 = *reinterpret_cast<const float4*>(xr + 4);
                u64 xp0 = pack2(u0.x, u0.y);
                u64 xp1 = pack2(u0.z, u0.w);
                u64 xp2 = pack2(u1.x, u1.y);
                u64 xp3 = pack2(u1.z, u1.w);
                #pragma unroll
                for (int j = 0; j < 8; ++j) {
                    float ev = (cc == 0) ? ef[j].x : (cc == 1) ? ef[j].y : (cc == 2) ? ef[j].z : ef[j].w;
                    u64 ed = pack_dup(ev);
                    ffma2(acc[j][0], ed, xp0);
                    ffma2(acc[j][1], ed, xp1);
                    ffma2(acc[j][2], ed, xp2);
                    ffma2(acc[j][3], ed, xp3);
                }
            }
        }

        // epilogue: d = (a - 2*dot) + esq, track argmin (first-index ties)
        #pragma unroll
        for (int j = 0; j < 8; ++j) {
            int k = kc * 128 + j * 16 + tc;
            float esq = __ldg(&g_esq[k]);
            #pragma unroll
            for (int i = 0; i < 4; ++i) {
                float d0, d1; unpack2(acc[j][i], d0, d1);
                int ii = i * 2;
                float a0 = as_[tr * 8 + ii];
                float a1 = as_[tr * 8 + ii + 1];
                float dd0 = __fadd_rn(__fsub_rn(a0, __fmul_rn(2.0f, d0)), esq);
                float dd1 = __fadd_rn(__fsub_rn(a1, __fmul_rn(2.0f, d1)), esq);
                if (dd0 < bestv[ii]     || (dd0 == bestv[ii]     && k < besti[ii]))     { bestv[ii] = dd0;     besti[ii] = k; }
                if (dd1 < bestv[ii + 1] || (dd1 == bestv[ii + 1] && k < besti[ii + 1])) { bestv[ii + 1] = dd1; besti[ii + 1] = k; }
            }
        }
    }

    // cross-lane argmin over the 16 code lanes (same warp half)
    #pragma unroll
    for (int off = 1; off < 16; off <<= 1) {
        #pragma unroll
        for (int i = 0; i < 8; ++i) {
            float ov = __shfl_xor_sync(0xffffffffu, bestv[i], off);
            int   oi = __shfl_xor_sync(0xffffffffu, besti[i], off);
            if (ov < bestv[i] || (ov == bestv[i] && oi < besti[i])) { bestv[i] = ov; besti[i] = oi; }
        }
    }
    if (tc == 0) {
        #pragma unroll
        for (int i = 0; i < 8; ++i) {
            int n = n0 + tr * 8 + i;
            g_idx[n]   = besti[i];
            outIdxF[n] = (float)besti[i];
        }
    }
}

// ---------------- quantize + loss partials + histogram ----------------
__global__ void __launch_bounds__(256) vq_quant(const float* __restrict__ inputs,
                                                const float* __restrict__ emb,
                                                float* __restrict__ outQ) {
    __shared__ double red[256];
    int tid = blockIdx.x * blockDim.x + threadIdx.x;   // 1,048,576 threads
    int n   = tid >> 4;
    int cg  = (tid & 15) << 2;
    int ki  = g_idx[n];
    int b   = n >> 10;
    int p   = n & 1023;

    float4 q = *reinterpret_cast<const float4*>(emb + (size_t)ki * CD + cg);
    const float* xb = inputs + (size_t)b * (CD * HW) + p;
    float x0 = xb[(size_t)(cg + 0) * HW];
    float x1 = xb[(size_t)(cg + 1) * HW];
    float x2 = xb[(size_t)(cg + 2) * HW];
    float x3 = xb[(size_t)(cg + 3) * HW];

    float e0 = __fsub_rn(q.x, x0);
    float e1 = __fsub_rn(q.y, x1);
    float e2 = __fsub_rn(q.z, x2);
    float e3 = __fsub_rn(q.w, x3);

    float4 o;                               // straight-through: x + (q - x), both rounded
    o.x = __fadd_rn(x0, e0);
    o.y = __fadd_rn(x1, e1);
    o.z = __fadd_rn(x2, e2);
    o.w = __fadd_rn(x3, e3);
    *reinterpret_cast<float4*>(outQ + (size_t)n * CD + cg) = o;

    double s = (double)__fmul_rn(e0, e0) + (double)__fmul_rn(e1, e1)
             + (double)__fmul_rn(e2, e2) + (double)__fmul_rn(e3, e3);

    if ((tid & 15) == 0) atomicAdd(&g_hist[ki], 1u);

    red[threadIdx.x] = s;
    __syncthreads();
    for (int off = 128; off > 0; off >>= 1) {
        if (threadIdx.x < off) red[threadIdx.x] += red[threadIdx.x + off];
        __syncthreads();
    }
    if (threadIdx.x == 0) atomicAdd(&g_loss, red[0]);
}

// ---------------- finalize: loss + perplexity ----------------
__global__ void vq_final(float* __restrict__ out) {
    __shared__ double red[256];
    int t = threadIdx.x;
    double s = 0.0;
    for (int k = t; k < KC; k += 256) {
        float cnt = (float)g_hist[k];
        float pr  = __fmul_rn(cnt, 1.0f / 65536.0f);        // exact (div by 2^16)
        float lg  = logf(__fadd_rn(pr, 1e-10f));
        s += (double)__fmul_rn(pr, lg);
    }
    red[t] = s;
    __syncthreads();
    for (int off = 128; off > 0; off >>= 1) {
        if (t < off) red[t] += red[t + off];
        __syncthreads();
    }
    if (t == 0) {
        float m    = (float)(g_loss / 4194304.0);
        float loss = __fadd_rn(m, __fmul_rn(0.25f, m));
        out[OFF_LOSS] = loss;
        float S = (float)red[0];
        out[OFF_PERP] = expf(-S);
    }
}

extern "C" void kernel_launch(void* const* d_in, const int* in_sizes, int n_in,
                              void* d_out, int out_size) {
    const float* inputs = (const float*)d_in[0];
    const float* emb    = (const float*)d_in[1];
    if (n_in >= 2 && in_sizes[0] == KC * CD && in_sizes[1] == NPTS * CD) {
        // defensive: metadata order swapped
        const float* tmp = inputs; inputs = emb; emb = tmp;
    }
    float* out = (float*)d_out;

    cudaFuncSetAttribute(vq_main, cudaFuncAttributeMaxDynamicSharedMemorySize, SMEM_BYTES);

    vq_init<<<1, 1024>>>();
    vq_esq<<<KC / 256, 256>>>(emb);
    vq_main<<<NPTS / MT, 256, SMEM_BYTES>>>(inputs, emb, out + OFF_IDX);
    vq_quant<<<(NPTS * 16) / 256, 256>>>(inputs, emb, out);
    vq_final<<<1, 256>>>(out);
}